// round 15
// baseline (speedup 1.0000x reference)
#include <cuda_runtime.h>
#include <math_constants.h>

#define C       384
#define DH      64
#define CTXC    128
#define BT      10
#define TFRAMES 5
#define NSTG    4
#define QSCALE  0.125f

// hw per stage: 6400, 1600, 400, 100
#define NPIX_TOTAL  85000          // sum of 10*hw
#define NQUAD_TOTAL 21250          // pixel quads
#define NCHUNK      8
#define CCHUNK      48             // 384 / 8
#define NUNITS      170000         // NQUAD_TOTAL * NCHUNK
#define VOUT_TOTAL  32640000       // 10*384*8500
#define ISEG        1600           // xbar i-segment
#define MAXSEG      4
#define SE_BLOCKS   110            // simexp blocks: 10*(7+2+1+1), 1024 px/block

__constant__ int c_hw[NSTG]      = {6400, 1600, 400, 100};
__constant__ int c_hw4[NSTG]     = {1600, 400, 100, 25};
__constant__ int c_pixoff[NSTG]  = {0, 64000, 80000, 84000};
__constant__ int c_qoff[NSTG]    = {0, 16000, 20000, 21000};
__constant__ int c_voutoff[NSTG] = {0, 24576000, 30720000, 32256000};
__constant__ int c_nseg[NSTG]    = {4, 1, 1, 1};
__constant__ int c_xboff[NSTG]   = {0, 960, 1200, 1440};   // k_xbar block offsets
__constant__ int c_seoff[NSTG]   = {0, 70, 90, 100};       // simexp block offsets
__constant__ int c_senb[NSTG]    = {7, 2, 1, 1};           // simexp blocks per (s,b)
#define XBAR_BLOCKS 1680

__device__ float g_wq  [NSTG * BT * C];
__device__ float g_y   [NSTG * BT * C];
__device__ float g_xbarp[MAXSEG * NSTG * BT * C];
__device__ float g_p   [NPIX_TOTAL];               // exp(sim)  (no max-sub)
__device__ float g_psum[SE_BLOCKS];                // per-block partial sums of exp
__device__ float g_simp[NCHUNK * NPIX_TOTAL];

__device__ __forceinline__ float4 ld4(const float* p) { return *(const float4*)p; }
__device__ __forceinline__ float4 ld4cs(const float* p) { return __ldcs((const float4*)p); }

__device__ __forceinline__ float warp_sum(float v) {
    #pragma unroll
    for (int o = 16; o > 0; o >>= 1) v += __shfl_down_sync(0xffffffffu, v, o);
    return v;
}

// ---------------------------------------------------------------------------
// K1: per-(stage,b) small algebra. Contiguous row-segment-per-thread (MLP),
// fixed-order smem combines.
// ---------------------------------------------------------------------------
__global__ __launch_bounds__(C)
void k_setup(const float* __restrict__ a0, const float* __restrict__ a1,
             const float* __restrict__ a2, const float* __restrict__ a3,
             const float* __restrict__ ctx_proj_w, const float* __restrict__ ctx_proj_b,
             const float* __restrict__ pos_emb,
             const float* __restrict__ qk_w, const float* __restrict__ ctx_qk_w,
             const float* __restrict__ ctx_v_w,
             const float* __restrict__ out_w, const float* __restrict__ out_b)
{
    int s = blockIdx.x / BT;
    int b = blockIdx.x % BT;
    const float* audio = (s == 0 ? a0 : s == 1 ? a1 : s == 2 ? a2 : a3) + b * CTXC;

    __shared__ float sh_au[CTXC];
    __shared__ float sh_a[C];      // a
    __shared__ float sh_ap[C];     // a + pe
    __shared__ float sh_part[128 * 3];
    __shared__ float sh_cqk[DH];
    __shared__ float sh_cv[DH];

    const int tid = threadIdx.x;

    if (tid < CTXC) sh_au[tid] = audio[tid];
    __syncthreads();

    // a[c] = Wp[c,:] @ audio + bp
    {
        const float* wp = ctx_proj_w + ((size_t)s * C + tid) * CTXC;
        float acc = 0.f;
        #pragma unroll
        for (int k = 0; k < CTXC; k += 4) {
            float4 w = ld4(wp + k);
            float4 u = ld4(sh_au + k);
            acc += w.x * u.x + w.y * u.y + w.z * u.z + w.w * u.w;
        }
        float av = acc + ctx_proj_b[s * C + tid];
        sh_a[tid]  = av;
        sh_ap[tid] = av + pos_emb[((size_t)s * TFRAMES + (b % TFRAMES)) * C + tid];
    }
    __syncthreads();

    // cqk[d] = Wcqk[d,:] @ (a+pe), cv[d] = Wcv[d,:] @ a
    {
        int chunk = tid >> 7;
        int r     = tid & 127;
        int m     = r >> 6;
        int d     = r & 63;
        const float* wrow = (m == 0 ? ctx_qk_w : ctx_v_w) + ((size_t)s * DH + d) * C + chunk * 128;
        const float* vec  = (m == 0 ? sh_ap : sh_a) + chunk * 128;
        float acc = 0.f;
        #pragma unroll
        for (int k = 0; k < 128; k += 4) {
            float4 w = ld4(wrow + k);
            float4 u = ld4(vec + k);
            acc += w.x * u.x + w.y * u.y + w.z * u.z + w.w * u.w;
        }
        sh_part[(m * 64 + d) * 3 + chunk] = acc;
    }
    __syncthreads();
    if (tid < 128) {
        float v = (sh_part[tid * 3 + 0] + sh_part[tid * 3 + 1]) + sh_part[tid * 3 + 2];
        if (tid < 64) sh_cqk[tid] = v; else sh_cv[tid - 64] = v;
    }
    __syncthreads();

    // y[c] = Wo[c,:] @ cv + bo
    {
        const float* wo = out_w + ((size_t)s * C + tid) * DH;
        float acc = 0.f;
        #pragma unroll
        for (int d = 0; d < DH; d += 4) {
            float4 w = ld4(wo + d);
            float4 t = ld4(sh_cv + d);
            acc += w.x * t.x + w.y * t.y + w.z * t.z + w.w * t.w;
        }
        g_y[(s * BT + b) * C + tid] = acc + out_b[s * C + tid];
    }

    // wq[c] = QSCALE * sum_d cqk[d] * Wqk[d,c]
    {
        float wv = 0.f;
        const float* wqk = qk_w + (size_t)s * DH * C + tid;
        #pragma unroll 16
        for (int d = 0; d < DH; d++) wv += sh_cqk[d] * wqk[(size_t)d * C];
        g_wq[(s * BT + b) * C + tid] = wv * QSCALE;
    }
}

// ---------------------------------------------------------------------------
// K2: FUSED sim + vout, TWO-PHASE. Phase 1 is a pure-load sim loop (LDGs can
// front-batch without interleaved STGs); phase 2 is a store-only vout
// broadcast (y re-loaded from L1). Warps interleave phases chip-wide so
// read/write BW still overlaps. unit = (c-chunk of 48, pixel-quad).
// ---------------------------------------------------------------------------
__global__ __launch_bounds__(256)
void k_sim_vout(const float* __restrict__ x0, const float* __restrict__ x1,
                const float* __restrict__ x2, const float* __restrict__ x3,
                const float* __restrict__ p0, const float* __restrict__ p1,
                const float* __restrict__ p2, const float* __restrict__ p3,
                float* __restrict__ out)
{
    int u = blockIdx.x * blockDim.x + threadIdx.x;
    if (u >= NUNITS) return;

    int chunk = u / NQUAD_TOTAL;
    int q     = u - chunk * NQUAD_TOTAL;

    int s;
    if      (q < 16000) s = 0;
    else if (q < 20000) s = 1;
    else if (q < 21000) s = 2;
    else                s = 3;

    const int hw    = c_hw[s];
    const int hw4   = c_hw4[s];
    const int local = q - c_qoff[s];
    const int b     = local / hw4;
    const int i     = (local - b * hw4) * 4;

    const float* x = (s == 0 ? x0 : s == 1 ? x1 : s == 2 ? x2 : x3);
    const float* p = (s == 0 ? p0 : s == 1 ? p1 : s == 2 ? p2 : p3);

    const int c0 = chunk * CCHUNK;
    const float* xb = x + ((size_t)b * C + c0) * hw + i;
    const float* pb = p + ((size_t)b * C + c0) * hw + i;
    const float* wq = g_wq + (s * BT + b) * C + c0;
    const float* yv = g_y  + (s * BT + b) * C + c0;
    float* vout = out + c_voutoff[s] + ((size_t)b * C + c0) * hw + i;

    // ---- Phase 1: pure-load sim accumulation ----
    float4 acc = make_float4(0.f, 0.f, 0.f, 0.f);
    #pragma unroll 3
    for (int c = 0; c < CCHUNK; c += 4) {
        const float* xc = xb + (size_t)c * hw;
        const float* pc = pb + (size_t)c * hw;
        float4 xv0 = ld4(xc);
        float4 pv0 = ld4cs(pc);
        float4 xv1 = ld4(xc + hw);
        float4 pv1 = ld4cs(pc + hw);
        float4 xv2 = ld4(xc + 2 * (size_t)hw);
        float4 pv2 = ld4cs(pc + 2 * (size_t)hw);
        float4 xv3 = ld4(xc + 3 * (size_t)hw);
        float4 pv3 = ld4cs(pc + 3 * (size_t)hw);
        float4 w4 = ld4(wq + c);

        acc.x = fmaf(xv0.x + pv0.x, w4.x, acc.x);
        acc.y = fmaf(xv0.y + pv0.y, w4.x, acc.y);
        acc.z = fmaf(xv0.z + pv0.z, w4.x, acc.z);
        acc.w = fmaf(xv0.w + pv0.w, w4.x, acc.w);
        acc.x = fmaf(xv1.x + pv1.x, w4.y, acc.x);
        acc.y = fmaf(xv1.y + pv1.y, w4.y, acc.y);
        acc.z = fmaf(xv1.z + pv1.z, w4.y, acc.z);
        acc.w = fmaf(xv1.w + pv1.w, w4.y, acc.w);
        acc.x = fmaf(xv2.x + pv2.x, w4.z, acc.x);
        acc.y = fmaf(xv2.y + pv2.y, w4.z, acc.y);
        acc.z = fmaf(xv2.z + pv2.z, w4.z, acc.z);
        acc.w = fmaf(xv2.w + pv2.w, w4.z, acc.w);
        acc.x = fmaf(xv3.x + pv3.x, w4.w, acc.x);
        acc.y = fmaf(xv3.y + pv3.y, w4.w, acc.y);
        acc.z = fmaf(xv3.z + pv3.z, w4.w, acc.z);
        acc.w = fmaf(xv3.w + pv3.w, w4.w, acc.w);
    }
    int gp = c_pixoff[s] + b * hw + i;
    *(float4*)(g_simp + chunk * NPIX_TOTAL + gp) = acc;

    // ---- Phase 2: store-only vout broadcast (y L1-hot from wq/yv line) ----
    #pragma unroll 3
    for (int c = 0; c < CCHUNK; c += 4) {
        float4 y4 = ld4(yv + c);
        float* vc = vout + (size_t)c * hw;
        __stcs((float4*)vc,                     make_float4(y4.x, y4.x, y4.x, y4.x));
        __stcs((float4*)(vc + hw),              make_float4(y4.y, y4.y, y4.y, y4.y));
        __stcs((float4*)(vc + 2 * (size_t)hw),  make_float4(y4.z, y4.z, y4.z, y4.z));
        __stcs((float4*)(vc + 3 * (size_t)hw),  make_float4(y4.w, y4.w, y4.w, y4.w));
    }
}

// ---------------------------------------------------------------------------
// K2b: parallel exp (NO max-sub; sim ~N(0,3.5^2), far from fp32 exp overflow).
// float4 path: thread reduces 4 pixels x 8 chunk arrays. 110 blocks.
// ---------------------------------------------------------------------------
__global__ __launch_bounds__(256)
void k_simexp()
{
    int blk = blockIdx.x;
    int s;
    if      (blk < 70)  s = 0;
    else if (blk < 90)  s = 1;
    else if (blk < 100) s = 2;
    else                s = 3;

    const int nb    = c_senb[s];
    const int local = blk - c_seoff[s];
    const int b     = local / nb;
    const int bi    = local - b * nb;
    const int hw    = c_hw[s];
    const int off   = c_pixoff[s] + b * hw;

    const int tid  = threadIdx.x;
    const int lane = tid & 31;
    const int warp = tid >> 5;
    const int i    = bi * 1024 + tid * 4;      // hw always multiple of 4

    __shared__ float sh_red[8];

    float esum = 0.f;
    if (i < hw) {
        int g = off + i;
        float4 v = ld4(g_simp + g);
        #pragma unroll
        for (int k = 1; k < NCHUNK; k++) {
            float4 t = ld4(g_simp + k * NPIX_TOTAL + g);
            v.x += t.x; v.y += t.y; v.z += t.z; v.w += t.w;
        }
        float4 e = make_float4(__expf(v.x), __expf(v.y), __expf(v.z), __expf(v.w));
        *(float4*)(g_p + g) = e;
        esum = (e.x + e.y) + (e.z + e.w);
    }
    float ssum = warp_sum(esum);
    if (lane == 0) sh_red[warp] = ssum;
    __syncthreads();
    if (tid < 8) {
        float v = sh_red[tid];
        #pragma unroll
        for (int o = 4; o > 0; o >>= 1) v += __shfl_down_sync(0xffu, v, o);
        if (tid == 0) g_psum[blk] = v;
    }
}

// ---------------------------------------------------------------------------
// K3: xbar partials (UNNORMALIZED). Block = (stage, b, 16-ch group, i-seg of
// 1600). Warp handles 2 channels. EXACT 46-reg variant (measured best:
// 28.0us, 60.9% DRAM) — no launch_bounds reg cap.
// ---------------------------------------------------------------------------
#define CG        16
#define NGROUPS   (C / CG)          // 24

__global__ __launch_bounds__(256)
void k_xbar(const float* __restrict__ x0, const float* __restrict__ x1,
            const float* __restrict__ x2, const float* __restrict__ x3)
{
    int blk = blockIdx.x;
    int s;
    if      (blk < 960)  s = 0;
    else if (blk < 1200) s = 1;
    else if (blk < 1440) s = 2;
    else                 s = 3;

    const int local = blk - c_xboff[s];
    const int nseg  = c_nseg[s];
    const int seg   = local % nseg;
    const int rest  = local / nseg;
    const int cg    = rest % NGROUPS;
    const int b     = rest / NGROUPS;
    const int hw    = c_hw[s];
    const int i0    = seg * ISEG;
    const int ilen  = (hw - i0 < ISEG) ? (hw - i0) : ISEG;

    const int lane = threadIdx.x & 31;
    const int warp = threadIdx.x >> 5;

    const float* x  = (s == 0 ? x0 : s == 1 ? x1 : s == 2 ? x2 : x3);
    const float* p  = g_p + c_pixoff[s] + b * hw + i0;

    const int c0 = cg * CG + warp * 2;
    const float* xc0 = x + ((size_t)b * C + c0) * hw + i0;
    const float* xc1 = xc0 + hw;

    float a00 = 0.f, a01 = 0.f, a02 = 0.f, a03 = 0.f;
    float a10 = 0.f, a11 = 0.f, a12 = 0.f, a13 = 0.f;
    for (int i = lane * 4; i < ilen; i += 128) {
        float4 pv  = ld4(p + i);
        float4 v0  = ld4(xc0 + i);
        float4 v1  = ld4(xc1 + i);
        a00 = fmaf(pv.x, v0.x, a00);
        a01 = fmaf(pv.y, v0.y, a01);
        a02 = fmaf(pv.z, v0.z, a02);
        a03 = fmaf(pv.w, v0.w, a03);
        a10 = fmaf(pv.x, v1.x, a10);
        a11 = fmaf(pv.y, v1.y, a11);
        a12 = fmaf(pv.z, v1.z, a12);
        a13 = fmaf(pv.w, v1.w, a13);
    }
    float r0 = warp_sum((a00 + a01) + (a02 + a03));
    float r1 = warp_sum((a10 + a11) + (a12 + a13));
    if (lane == 0) {
        int base = seg * (NSTG * BT * C) + (s * BT + b) * C + c0;
        g_xbarp[base]     = r0;
        g_xbarp[base + 1] = r1;
    }
}

// ---------------------------------------------------------------------------
// K4: reconstruct rinv from per-block exp sums (fixed order), combine xbar
// partials (fixed order), then aout = bco + Wco@(Wv@xbar).
// ---------------------------------------------------------------------------
__global__ __launch_bounds__(C)
void k_aout(const float* __restrict__ v_w,
            const float* __restrict__ ctx_out_w,
            const float* __restrict__ ctx_out_b,
            float* __restrict__ out)
{
    int s = blockIdx.x / BT;
    int b = blockIdx.x % BT;
    __shared__ float sh_ps[32];
    __shared__ float sh_xb[C];
    __shared__ float sh_part[DH * 6];
    __shared__ float sh_t[DH];

    const int tid = threadIdx.x;
    const int sb  = s * BT + b;
    const int nb  = c_senb[s];

    if (tid < nb) sh_ps[tid] = g_psum[c_seoff[s] + b * nb + tid];
    __syncthreads();

    // every thread computes the identical fixed-order sum -> identical rinv
    float ssum = 0.f;
    for (int k = 0; k < nb; k++) ssum += sh_ps[k];
    const float rinv = 1.f / ssum;

    // combine segment partials (fixed order), normalize
    {
        int idx = sb * C + tid;
        float v = g_xbarp[idx];
        if (s == 0) {
            v = (v + g_xbarp[NSTG * BT * C + idx]) +
                (g_xbarp[2 * NSTG * BT * C + idx] + g_xbarp[3 * NSTG * BT * C + idx]);
        }
        sh_xb[tid] = v * rinv;
    }
    __syncthreads();

    // t[d] = Wv[d,:] @ xbar
    {
        int chunk = tid >> 6;
        int d     = tid & 63;
        const float* wv  = v_w + ((size_t)s * DH + d) * C + chunk * 64;
        const float* vec = sh_xb + chunk * 64;
        float acc = 0.f;
        #pragma unroll
        for (int k = 0; k < 64; k += 4) {
            float4 w = ld4(wv + k);
            float4 u = ld4(vec + k);
            acc += w.x * u.x + w.y * u.y + w.z * u.z + w.w * u.w;
        }
        sh_part[d * 6 + chunk] = acc;
    }
    __syncthreads();
    if (tid < DH) {
        const float* pp = sh_part + tid * 6;
        sh_t[tid] = ((pp[0] + pp[1]) + (pp[2] + pp[3])) + (pp[4] + pp[5]);
    }
    __syncthreads();

    // aout[c] = Wco[c,:] @ t + bco
    {
        const float* wco = ctx_out_w + ((size_t)s * C + tid) * DH;
        float acc = 0.f;
        #pragma unroll
        for (int d = 0; d < DH; d += 4) {
            float4 w = ld4(wco + d);
            float4 t = ld4(sh_t + d);
            acc += w.x * t.x + w.y * t.y + w.z * t.z + w.w * t.w;
        }
        out[VOUT_TOTAL + sb * C + tid] = acc + ctx_out_b[s * C + tid];
    }
}

// ---------------------------------------------------------------------------
extern "C" void kernel_launch(void* const* d_in, const int* in_sizes, int n_in,
                              void* d_out, int out_size)
{
    const float *fm[NSTG], *ps[NSTG], *au[NSTG];
    bool dict_order = (in_sizes[1] == in_sizes[0]);
    if (dict_order) {
        for (int s = 0; s < NSTG; s++) {
            fm[s] = (const float*)d_in[3 * s + 0];
            ps[s] = (const float*)d_in[3 * s + 1];
            au[s] = (const float*)d_in[3 * s + 2];
        }
    } else {
        for (int s = 0; s < NSTG; s++) {
            fm[s] = (const float*)d_in[s];
            au[s] = (const float*)d_in[4 + s];
            ps[s] = (const float*)d_in[8 + s];
        }
    }
    const float* ctx_proj_w = (const float*)d_in[12];
    const float* ctx_proj_b = (const float*)d_in[13];
    const float* pos_emb    = (const float*)d_in[14];
    const float* qk_w       = (const float*)d_in[15];
    const float* ctx_qk_w   = (const float*)d_in[16];
    const float* v_w        = (const float*)d_in[17];
    const float* ctx_v_w    = (const float*)d_in[18];
    const float* out_w      = (const float*)d_in[19];
    const float* out_b      = (const float*)d_in[20];
    const float* ctx_out_w  = (const float*)d_in[21];
    const float* ctx_out_b  = (const float*)d_in[22];

    float* out = (float*)d_out;

    k_setup<<<NSTG * BT, C>>>(au[0], au[1], au[2], au[3],
                              ctx_proj_w, ctx_proj_b, pos_emb,
                              qk_w, ctx_qk_w, ctx_v_w, out_w, out_b);

    k_sim_vout<<<(NUNITS + 255) / 256, 256>>>(fm[0], fm[1], fm[2], fm[3],
                                              ps[0], ps[1], ps[2], ps[3], out);

    k_simexp<<<SE_BLOCKS, 256>>>();

    k_xbar<<<XBAR_BLOCKS, 256>>>(fm[0], fm[1], fm[2], fm[3]);

    k_aout<<<NSTG * BT, C>>>(v_w, ctx_out_w, ctx_out_b, out);
}

// round 16
// speedup vs baseline: 1.0975x; 1.0975x over previous
#include <cuda_runtime.h>
#include <math_constants.h>

#define C       384
#define DH      64
#define CTXC    128
#define BT      10
#define TFRAMES 5
#define NSTG    4
#define QSCALE  0.125f

// hw per stage: 6400, 1600, 400, 100
#define NPIX_TOTAL  85000          // sum of 10*hw
#define NQUAD_TOTAL 21250          // pixel quads
#define NCHUNK      8
#define CCHUNK      48             // 384 / 8
#define NUNITS      170000         // NQUAD_TOTAL * NCHUNK
#define VOUT_TOTAL  32640000       // 10*384*8500
#define ISEG        1600           // xbar i-segment
#define MAXSEG      4
#define SE_BLOCKS   110            // simexp blocks: 10*(7+2+1+1), 1024 px/block

__constant__ int c_hw[NSTG]      = {6400, 1600, 400, 100};
__constant__ int c_hw4[NSTG]     = {1600, 400, 100, 25};
__constant__ int c_pixoff[NSTG]  = {0, 64000, 80000, 84000};
__constant__ int c_qoff[NSTG]    = {0, 16000, 20000, 21000};
__constant__ int c_voutoff[NSTG] = {0, 24576000, 30720000, 32256000};
__constant__ int c_nseg[NSTG]    = {4, 1, 1, 1};
__constant__ int c_xboff[NSTG]   = {0, 960, 1200, 1440};   // k_xbar block offsets
__constant__ int c_seoff[NSTG]   = {0, 70, 90, 100};       // simexp block offsets
__constant__ int c_senb[NSTG]    = {7, 2, 1, 1};           // simexp blocks per (s,b)
#define XBAR_BLOCKS 1680

__device__ float g_wq  [NSTG * BT * C];
__device__ float g_y   [NSTG * BT * C];
__device__ float g_xbarp[MAXSEG * NSTG * BT * C];
__device__ float g_p   [NPIX_TOTAL];               // exp(sim)  (no max-sub)
__device__ float g_psum[SE_BLOCKS];                // per-block partial sums of exp
__device__ float g_simp[NCHUNK * NPIX_TOTAL];

__device__ __forceinline__ float4 ld4(const float* p) { return *(const float4*)p; }
__device__ __forceinline__ float4 ld4cs(const float* p) { return __ldcs((const float4*)p); }

__device__ __forceinline__ float warp_sum(float v) {
    #pragma unroll
    for (int o = 16; o > 0; o >>= 1) v += __shfl_down_sync(0xffffffffu, v, o);
    return v;
}

// ---------------------------------------------------------------------------
// K1: per-(stage,b) small algebra. Contiguous row-segment-per-thread (MLP),
// fixed-order smem combines.
// ---------------------------------------------------------------------------
__global__ __launch_bounds__(C)
void k_setup(const float* __restrict__ a0, const float* __restrict__ a1,
             const float* __restrict__ a2, const float* __restrict__ a3,
             const float* __restrict__ ctx_proj_w, const float* __restrict__ ctx_proj_b,
             const float* __restrict__ pos_emb,
             const float* __restrict__ qk_w, const float* __restrict__ ctx_qk_w,
             const float* __restrict__ ctx_v_w,
             const float* __restrict__ out_w, const float* __restrict__ out_b)
{
    int s = blockIdx.x / BT;
    int b = blockIdx.x % BT;
    const float* audio = (s == 0 ? a0 : s == 1 ? a1 : s == 2 ? a2 : a3) + b * CTXC;

    __shared__ float sh_au[CTXC];
    __shared__ float sh_a[C];      // a
    __shared__ float sh_ap[C];     // a + pe
    __shared__ float sh_part[128 * 3];
    __shared__ float sh_cqk[DH];
    __shared__ float sh_cv[DH];

    const int tid = threadIdx.x;

    if (tid < CTXC) sh_au[tid] = audio[tid];
    __syncthreads();

    // a[c] = Wp[c,:] @ audio + bp
    {
        const float* wp = ctx_proj_w + ((size_t)s * C + tid) * CTXC;
        float acc = 0.f;
        #pragma unroll
        for (int k = 0; k < CTXC; k += 4) {
            float4 w = ld4(wp + k);
            float4 u = ld4(sh_au + k);
            acc += w.x * u.x + w.y * u.y + w.z * u.z + w.w * u.w;
        }
        float av = acc + ctx_proj_b[s * C + tid];
        sh_a[tid]  = av;
        sh_ap[tid] = av + pos_emb[((size_t)s * TFRAMES + (b % TFRAMES)) * C + tid];
    }
    __syncthreads();

    // cqk[d] = Wcqk[d,:] @ (a+pe), cv[d] = Wcv[d,:] @ a
    {
        int chunk = tid >> 7;
        int r     = tid & 127;
        int m     = r >> 6;
        int d     = r & 63;
        const float* wrow = (m == 0 ? ctx_qk_w : ctx_v_w) + ((size_t)s * DH + d) * C + chunk * 128;
        const float* vec  = (m == 0 ? sh_ap : sh_a) + chunk * 128;
        float acc = 0.f;
        #pragma unroll
        for (int k = 0; k < 128; k += 4) {
            float4 w = ld4(wrow + k);
            float4 u = ld4(vec + k);
            acc += w.x * u.x + w.y * u.y + w.z * u.z + w.w * u.w;
        }
        sh_part[(m * 64 + d) * 3 + chunk] = acc;
    }
    __syncthreads();
    if (tid < 128) {
        float v = (sh_part[tid * 3 + 0] + sh_part[tid * 3 + 1]) + sh_part[tid * 3 + 2];
        if (tid < 64) sh_cqk[tid] = v; else sh_cv[tid - 64] = v;
    }
    __syncthreads();

    // y[c] = Wo[c,:] @ cv + bo
    {
        const float* wo = out_w + ((size_t)s * C + tid) * DH;
        float acc = 0.f;
        #pragma unroll
        for (int d = 0; d < DH; d += 4) {
            float4 w = ld4(wo + d);
            float4 t = ld4(sh_cv + d);
            acc += w.x * t.x + w.y * t.y + w.z * t.z + w.w * t.w;
        }
        g_y[(s * BT + b) * C + tid] = acc + out_b[s * C + tid];
    }

    // wq[c] = QSCALE * sum_d cqk[d] * Wqk[d,c]
    {
        float wv = 0.f;
        const float* wqk = qk_w + (size_t)s * DH * C + tid;
        #pragma unroll 16
        for (int d = 0; d < DH; d++) wv += sh_cqk[d] * wqk[(size_t)d * C];
        g_wq[(s * BT + b) * C + tid] = wv * QSCALE;
    }
}

// ---------------------------------------------------------------------------
// K2: FUSED sim + vout, INTERLEAVED (measured-best form). unit = (c-chunk of
// 48, pixel-quad), 170k threads. x caching, pos streaming, vout streaming.
// ---------------------------------------------------------------------------
__global__ __launch_bounds__(256)
void k_sim_vout(const float* __restrict__ x0, const float* __restrict__ x1,
                const float* __restrict__ x2, const float* __restrict__ x3,
                const float* __restrict__ p0, const float* __restrict__ p1,
                const float* __restrict__ p2, const float* __restrict__ p3,
                float* __restrict__ out)
{
    int u = blockIdx.x * blockDim.x + threadIdx.x;
    if (u >= NUNITS) return;

    int chunk = u / NQUAD_TOTAL;
    int q     = u - chunk * NQUAD_TOTAL;

    int s;
    if      (q < 16000) s = 0;
    else if (q < 20000) s = 1;
    else if (q < 21000) s = 2;
    else                s = 3;

    const int hw    = c_hw[s];
    const int hw4   = c_hw4[s];
    const int local = q - c_qoff[s];
    const int b     = local / hw4;
    const int i     = (local - b * hw4) * 4;

    const float* x = (s == 0 ? x0 : s == 1 ? x1 : s == 2 ? x2 : x3);
    const float* p = (s == 0 ? p0 : s == 1 ? p1 : s == 2 ? p2 : p3);

    const int c0 = chunk * CCHUNK;
    const float* xb = x + ((size_t)b * C + c0) * hw + i;
    const float* pb = p + ((size_t)b * C + c0) * hw + i;
    const float* wq = g_wq + (s * BT + b) * C + c0;
    const float* yv = g_y  + (s * BT + b) * C + c0;
    float* vout = out + c_voutoff[s] + ((size_t)b * C + c0) * hw + i;

    float4 acc = make_float4(0.f, 0.f, 0.f, 0.f);
    #pragma unroll 3
    for (int c = 0; c < CCHUNK; c += 4) {
        const float* xc = xb + (size_t)c * hw;
        const float* pc = pb + (size_t)c * hw;
        float4 xv0 = ld4(xc);
        float4 pv0 = ld4cs(pc);
        float4 xv1 = ld4(xc + hw);
        float4 pv1 = ld4cs(pc + hw);
        float4 xv2 = ld4(xc + 2 * (size_t)hw);
        float4 pv2 = ld4cs(pc + 2 * (size_t)hw);
        float4 xv3 = ld4(xc + 3 * (size_t)hw);
        float4 pv3 = ld4cs(pc + 3 * (size_t)hw);
        float4 w4 = ld4(wq + c);
        float4 y4 = ld4(yv + c);

        acc.x = fmaf(xv0.x + pv0.x, w4.x, acc.x);
        acc.y = fmaf(xv0.y + pv0.y, w4.x, acc.y);
        acc.z = fmaf(xv0.z + pv0.z, w4.x, acc.z);
        acc.w = fmaf(xv0.w + pv0.w, w4.x, acc.w);
        acc.x = fmaf(xv1.x + pv1.x, w4.y, acc.x);
        acc.y = fmaf(xv1.y + pv1.y, w4.y, acc.y);
        acc.z = fmaf(xv1.z + pv1.z, w4.y, acc.z);
        acc.w = fmaf(xv1.w + pv1.w, w4.y, acc.w);
        acc.x = fmaf(xv2.x + pv2.x, w4.z, acc.x);
        acc.y = fmaf(xv2.y + pv2.y, w4.z, acc.y);
        acc.z = fmaf(xv2.z + pv2.z, w4.z, acc.z);
        acc.w = fmaf(xv2.w + pv2.w, w4.z, acc.w);
        acc.x = fmaf(xv3.x + pv3.x, w4.w, acc.x);
        acc.y = fmaf(xv3.y + pv3.y, w4.w, acc.y);
        acc.z = fmaf(xv3.z + pv3.z, w4.w, acc.z);
        acc.w = fmaf(xv3.w + pv3.w, w4.w, acc.w);

        float* vc = vout + (size_t)c * hw;
        __stcs((float4*)vc,                     make_float4(y4.x, y4.x, y4.x, y4.x));
        __stcs((float4*)(vc + hw),              make_float4(y4.y, y4.y, y4.y, y4.y));
        __stcs((float4*)(vc + 2 * (size_t)hw),  make_float4(y4.z, y4.z, y4.z, y4.z));
        __stcs((float4*)(vc + 3 * (size_t)hw),  make_float4(y4.w, y4.w, y4.w, y4.w));
    }
    int gp = c_pixoff[s] + b * hw + i;
    *(float4*)(g_simp + chunk * NPIX_TOTAL + gp) = acc;
}

// ---------------------------------------------------------------------------
// K2b: parallel exp (NO max-sub; sim ~N(0,3.5^2), far from fp32 exp overflow).
// float4 path: thread reduces 4 pixels x 8 chunk arrays (32 coalesced float4
// loads). Block = 1024-pixel tile of one (s,b). 110 blocks.
// ---------------------------------------------------------------------------
__global__ __launch_bounds__(256)
void k_simexp()
{
    int blk = blockIdx.x;
    int s;
    if      (blk < 70)  s = 0;
    else if (blk < 90)  s = 1;
    else if (blk < 100) s = 2;
    else                s = 3;

    const int nb    = c_senb[s];
    const int local = blk - c_seoff[s];
    const int b     = local / nb;
    const int bi    = local - b * nb;
    const int hw    = c_hw[s];
    const int off   = c_pixoff[s] + b * hw;

    const int tid  = threadIdx.x;
    const int lane = tid & 31;
    const int warp = tid >> 5;
    const int i    = bi * 1024 + tid * 4;      // hw always multiple of 4

    __shared__ float sh_red[8];

    float esum = 0.f;
    if (i < hw) {
        int g = off + i;
        float4 v = ld4(g_simp + g);
        #pragma unroll
        for (int k = 1; k < NCHUNK; k++) {
            float4 t = ld4(g_simp + k * NPIX_TOTAL + g);
            v.x += t.x; v.y += t.y; v.z += t.z; v.w += t.w;
        }
        float4 e = make_float4(__expf(v.x), __expf(v.y), __expf(v.z), __expf(v.w));
        *(float4*)(g_p + g) = e;
        esum = (e.x + e.y) + (e.z + e.w);
    }
    float ssum = warp_sum(esum);
    if (lane == 0) sh_red[warp] = ssum;
    __syncthreads();
    if (tid < 8) {
        float v = sh_red[tid];
        #pragma unroll
        for (int o = 4; o > 0; o >>= 1) v += __shfl_down_sync(0xffu, v, o);
        if (tid == 0) g_psum[blk] = v;
    }
}

// ---------------------------------------------------------------------------
// K3: xbar partials (UNNORMALIZED). Block = (stage, b, 16-ch group, i-seg of
// 1600). Warp handles 2 channels. 46-reg measured-best variant.
// ---------------------------------------------------------------------------
#define CG        16
#define NGROUPS   (C / CG)          // 24

__global__ __launch_bounds__(256)
void k_xbar(const float* __restrict__ x0, const float* __restrict__ x1,
            const float* __restrict__ x2, const float* __restrict__ x3)
{
    int blk = blockIdx.x;
    int s;
    if      (blk < 960)  s = 0;
    else if (blk < 1200) s = 1;
    else if (blk < 1440) s = 2;
    else                 s = 3;

    const int local = blk - c_xboff[s];
    const int nseg  = c_nseg[s];
    const int seg   = local % nseg;
    const int rest  = local / nseg;
    const int cg    = rest % NGROUPS;
    const int b     = rest / NGROUPS;
    const int hw    = c_hw[s];
    const int i0    = seg * ISEG;
    const int ilen  = (hw - i0 < ISEG) ? (hw - i0) : ISEG;

    const int lane = threadIdx.x & 31;
    const int warp = threadIdx.x >> 5;

    const float* x  = (s == 0 ? x0 : s == 1 ? x1 : s == 2 ? x2 : x3);
    const float* p  = g_p + c_pixoff[s] + b * hw + i0;

    const int c0 = cg * CG + warp * 2;
    const float* xc0 = x + ((size_t)b * C + c0) * hw + i0;
    const float* xc1 = xc0 + hw;

    float a00 = 0.f, a01 = 0.f, a02 = 0.f, a03 = 0.f;
    float a10 = 0.f, a11 = 0.f, a12 = 0.f, a13 = 0.f;
    for (int i = lane * 4; i < ilen; i += 128) {
        float4 pv  = ld4(p + i);
        float4 v0  = ld4(xc0 + i);
        float4 v1  = ld4(xc1 + i);
        a00 = fmaf(pv.x, v0.x, a00);
        a01 = fmaf(pv.y, v0.y, a01);
        a02 = fmaf(pv.z, v0.z, a02);
        a03 = fmaf(pv.w, v0.w, a03);
        a10 = fmaf(pv.x, v1.x, a10);
        a11 = fmaf(pv.y, v1.y, a11);
        a12 = fmaf(pv.z, v1.z, a12);
        a13 = fmaf(pv.w, v1.w, a13);
    }
    float r0 = warp_sum((a00 + a01) + (a02 + a03));
    float r1 = warp_sum((a10 + a11) + (a12 + a13));
    if (lane == 0) {
        int base = seg * (NSTG * BT * C) + (s * BT + b) * C + c0;
        g_xbarp[base]     = r0;
        g_xbarp[base + 1] = r1;
    }
}

// ---------------------------------------------------------------------------
// K4: reconstruct rinv from per-block exp sums (fixed order), combine xbar
// partials (fixed order), then aout = bco + Wco@(Wv@xbar).
// ---------------------------------------------------------------------------
__global__ __launch_bounds__(C)
void k_aout(const float* __restrict__ v_w,
            const float* __restrict__ ctx_out_w,
            const float* __restrict__ ctx_out_b,
            float* __restrict__ out)
{
    int s = blockIdx.x / BT;
    int b = blockIdx.x % BT;
    __shared__ float sh_ps[32];
    __shared__ float sh_xb[C];
    __shared__ float sh_part[DH * 6];
    __shared__ float sh_t[DH];

    const int tid = threadIdx.x;
    const int sb  = s * BT + b;
    const int nb  = c_senb[s];

    if (tid < nb) sh_ps[tid] = g_psum[c_seoff[s] + b * nb + tid];
    __syncthreads();

    // every thread computes the identical fixed-order sum -> identical rinv
    float ssum = 0.f;
    for (int k = 0; k < nb; k++) ssum += sh_ps[k];
    const float rinv = 1.f / ssum;

    // combine segment partials (fixed order), normalize
    {
        int idx = sb * C + tid;
        float v = g_xbarp[idx];
        if (s == 0) {
            v = (v + g_xbarp[NSTG * BT * C + idx]) +
                (g_xbarp[2 * NSTG * BT * C + idx] + g_xbarp[3 * NSTG * BT * C + idx]);
        }
        sh_xb[tid] = v * rinv;
    }
    __syncthreads();

    // t[d] = Wv[d,:] @ xbar
    {
        int chunk = tid >> 6;
        int d     = tid & 63;
        const float* wv  = v_w + ((size_t)s * DH + d) * C + chunk * 64;
        const float* vec = sh_xb + chunk * 64;
        float acc = 0.f;
        #pragma unroll
        for (int k = 0; k < 64; k += 4) {
            float4 w = ld4(wv + k);
            float4 u = ld4(vec + k);
            acc += w.x * u.x + w.y * u.y + w.z * u.z + w.w * u.w;
        }
        sh_part[d * 6 + chunk] = acc;
    }
    __syncthreads();
    if (tid < DH) {
        const float* pp = sh_part + tid * 6;
        sh_t[tid] = ((pp[0] + pp[1]) + (pp[2] + pp[3])) + (pp[4] + pp[5]);
    }
    __syncthreads();

    // aout[c] = Wco[c,:] @ t + bco
    {
        const float* wco = ctx_out_w + ((size_t)s * C + tid) * DH;
        float acc = 0.f;
        #pragma unroll
        for (int d = 0; d < DH; d += 4) {
            float4 w = ld4(wco + d);
            float4 t = ld4(sh_t + d);
            acc += w.x * t.x + w.y * t.y + w.z * t.z + w.w * t.w;
        }
        out[VOUT_TOTAL + sb * C + tid] = acc + ctx_out_b[s * C + tid];
    }
}

// ---------------------------------------------------------------------------
extern "C" void kernel_launch(void* const* d_in, const int* in_sizes, int n_in,
                              void* d_out, int out_size)
{
    const float *fm[NSTG], *ps[NSTG], *au[NSTG];
    bool dict_order = (in_sizes[1] == in_sizes[0]);
    if (dict_order) {
        for (int s = 0; s < NSTG; s++) {
            fm[s] = (const float*)d_in[3 * s + 0];
            ps[s] = (const float*)d_in[3 * s + 1];
            au[s] = (const float*)d_in[3 * s + 2];
        }
    } else {
        for (int s = 0; s < NSTG; s++) {
            fm[s] = (const float*)d_in[s];
            au[s] = (const float*)d_in[4 + s];
            ps[s] = (const float*)d_in[8 + s];
        }
    }
    const float* ctx_proj_w = (const float*)d_in[12];
    const float* ctx_proj_b = (const float*)d_in[13];
    const float* pos_emb    = (const float*)d_in[14];
    const float* qk_w       = (const float*)d_in[15];
    const float* ctx_qk_w   = (const float*)d_in[16];
    const float* v_w        = (const float*)d_in[17];
    const float* ctx_v_w    = (const float*)d_in[18];
    const float* out_w      = (const float*)d_in[19];
    const float* out_b      = (const float*)d_in[20];
    const float* ctx_out_w  = (const float*)d_in[21];
    const float* ctx_out_b  = (const float*)d_in[22];

    float* out = (float*)d_out;

    k_setup<<<NSTG * BT, C>>>(au[0], au[1], au[2], au[3],
                              ctx_proj_w, ctx_proj_b, pos_emb,
                              qk_w, ctx_qk_w, ctx_v_w, out_w, out_b);

    k_sim_vout<<<(NUNITS + 255) / 256, 256>>>(fm[0], fm[1], fm[2], fm[3],
                                              ps[0], ps[1], ps[2], ps[3], out);

    k_simexp<<<SE_BLOCKS, 256>>>();

    k_xbar<<<XBAR_BLOCKS, 256>>>(fm[0], fm[1], fm[2], fm[3]);

    k_aout<<<NSTG * BT, C>>>(v_w, ctx_out_w, ctx_out_b, out);
}

// round 17
// speedup vs baseline: 1.1000x; 1.0023x over previous
#include <cuda_runtime.h>
#include <math_constants.h>

#define C       384
#define DH      64
#define CTXC    128
#define BT      10
#define TFRAMES 5
#define NSTG    4
#define QSCALE  0.125f

// hw per stage: 6400, 1600, 400, 100
#define NPIX_TOTAL  85000          // sum of 10*hw
#define NQUAD_TOTAL 21250          // pixel quads
#define NCHUNK      12
#define CCHUNK      32             // 384 / 12
#define NUNITS      255000         // NQUAD_TOTAL * NCHUNK
#define VOUT_TOTAL  32640000       // 10*384*8500
#define ISEG        1600           // xbar i-segment
#define MAXSEG      4
#define SE_BLOCKS   110            // simexp blocks: 10*(7+2+1+1), 1024 px/block

__constant__ int c_hw[NSTG]      = {6400, 1600, 400, 100};
__constant__ int c_hw4[NSTG]     = {1600, 400, 100, 25};
__constant__ int c_pixoff[NSTG]  = {0, 64000, 80000, 84000};
__constant__ int c_qoff[NSTG]    = {0, 16000, 20000, 21000};
__constant__ int c_voutoff[NSTG] = {0, 24576000, 30720000, 32256000};
__constant__ int c_nseg[NSTG]    = {4, 1, 1, 1};
__constant__ int c_xboff[NSTG]   = {0, 960, 1200, 1440};   // k_xbar block offsets
__constant__ int c_seoff[NSTG]   = {0, 70, 90, 100};       // simexp block offsets
__constant__ int c_senb[NSTG]    = {7, 2, 1, 1};           // simexp blocks per (s,b)
#define XBAR_BLOCKS 1680

__device__ float g_wq  [NSTG * BT * C];
__device__ float g_y   [NSTG * BT * C];
__device__ float g_xbarp[MAXSEG * NSTG * BT * C];
__device__ float g_p   [NPIX_TOTAL];               // exp(sim)  (no max-sub)
__device__ float g_psum[SE_BLOCKS];                // per-block partial sums of exp
__device__ float g_simp[NCHUNK * NPIX_TOTAL];

__device__ __forceinline__ float4 ld4(const float* p) { return *(const float4*)p; }
__device__ __forceinline__ float4 ld4cs(const float* p) { return __ldcs((const float4*)p); }

__device__ __forceinline__ float warp_sum(float v) {
    #pragma unroll
    for (int o = 16; o > 0; o >>= 1) v += __shfl_down_sync(0xffffffffu, v, o);
    return v;
}

// ---------------------------------------------------------------------------
// K1: per-(stage,b) small algebra. Contiguous row-segment-per-thread (MLP),
// fixed-order smem combines.
// ---------------------------------------------------------------------------
__global__ __launch_bounds__(C)
void k_setup(const float* __restrict__ a0, const float* __restrict__ a1,
             const float* __restrict__ a2, const float* __restrict__ a3,
             const float* __restrict__ ctx_proj_w, const float* __restrict__ ctx_proj_b,
             const float* __restrict__ pos_emb,
             const float* __restrict__ qk_w, const float* __restrict__ ctx_qk_w,
             const float* __restrict__ ctx_v_w,
             const float* __restrict__ out_w, const float* __restrict__ out_b)
{
    int s = blockIdx.x / BT;
    int b = blockIdx.x % BT;
    const float* audio = (s == 0 ? a0 : s == 1 ? a1 : s == 2 ? a2 : a3) + b * CTXC;

    __shared__ float sh_au[CTXC];
    __shared__ float sh_a[C];      // a
    __shared__ float sh_ap[C];     // a + pe
    __shared__ float sh_part[128 * 3];
    __shared__ float sh_cqk[DH];
    __shared__ float sh_cv[DH];

    const int tid = threadIdx.x;

    if (tid < CTXC) sh_au[tid] = audio[tid];
    __syncthreads();

    // a[c] = Wp[c,:] @ audio + bp
    {
        const float* wp = ctx_proj_w + ((size_t)s * C + tid) * CTXC;
        float acc = 0.f;
        #pragma unroll
        for (int k = 0; k < CTXC; k += 4) {
            float4 w = ld4(wp + k);
            float4 u = ld4(sh_au + k);
            acc += w.x * u.x + w.y * u.y + w.z * u.z + w.w * u.w;
        }
        float av = acc + ctx_proj_b[s * C + tid];
        sh_a[tid]  = av;
        sh_ap[tid] = av + pos_emb[((size_t)s * TFRAMES + (b % TFRAMES)) * C + tid];
    }
    __syncthreads();

    // cqk[d] = Wcqk[d,:] @ (a+pe), cv[d] = Wcv[d,:] @ a
    {
        int chunk = tid >> 7;
        int r     = tid & 127;
        int m     = r >> 6;
        int d     = r & 63;
        const float* wrow = (m == 0 ? ctx_qk_w : ctx_v_w) + ((size_t)s * DH + d) * C + chunk * 128;
        const float* vec  = (m == 0 ? sh_ap : sh_a) + chunk * 128;
        float acc = 0.f;
        #pragma unroll
        for (int k = 0; k < 128; k += 4) {
            float4 w = ld4(wrow + k);
            float4 u = ld4(vec + k);
            acc += w.x * u.x + w.y * u.y + w.z * u.z + w.w * u.w;
        }
        sh_part[(m * 64 + d) * 3 + chunk] = acc;
    }
    __syncthreads();
    if (tid < 128) {
        float v = (sh_part[tid * 3 + 0] + sh_part[tid * 3 + 1]) + sh_part[tid * 3 + 2];
        if (tid < 64) sh_cqk[tid] = v; else sh_cv[tid - 64] = v;
    }
    __syncthreads();

    // y[c] = Wo[c,:] @ cv + bo
    {
        const float* wo = out_w + ((size_t)s * C + tid) * DH;
        float acc = 0.f;
        #pragma unroll
        for (int d = 0; d < DH; d += 4) {
            float4 w = ld4(wo + d);
            float4 t = ld4(sh_cv + d);
            acc += w.x * t.x + w.y * t.y + w.z * t.z + w.w * t.w;
        }
        g_y[(s * BT + b) * C + tid] = acc + out_b[s * C + tid];
    }

    // wq[c] = QSCALE * sum_d cqk[d] * Wqk[d,c]
    {
        float wv = 0.f;
        const float* wqk = qk_w + (size_t)s * DH * C + tid;
        #pragma unroll 16
        for (int d = 0; d < DH; d++) wv += sh_cqk[d] * wqk[(size_t)d * C];
        g_wq[(s * BT + b) * C + tid] = wv * QSCALE;
    }
}

// ---------------------------------------------------------------------------
// K2: FUSED sim + vout, INTERLEAVED. unit = (c-chunk of 32, pixel-quad),
// 255k threads (NCHUNK=12 — more warps => more bytes in flight).
// x caching, pos streaming, vout streaming.
// ---------------------------------------------------------------------------
__global__ __launch_bounds__(256)
void k_sim_vout(const float* __restrict__ x0, const float* __restrict__ x1,
                const float* __restrict__ x2, const float* __restrict__ x3,
                const float* __restrict__ p0, const float* __restrict__ p1,
                const float* __restrict__ p2, const float* __restrict__ p3,
                float* __restrict__ out)
{
    int u = blockIdx.x * blockDim.x + threadIdx.x;
    if (u >= NUNITS) return;

    int chunk = u / NQUAD_TOTAL;
    int q     = u - chunk * NQUAD_TOTAL;

    int s;
    if      (q < 16000) s = 0;
    else if (q < 20000) s = 1;
    else if (q < 21000) s = 2;
    else                s = 3;

    const int hw    = c_hw[s];
    const int hw4   = c_hw4[s];
    const int local = q - c_qoff[s];
    const int b     = local / hw4;
    const int i     = (local - b * hw4) * 4;

    const float* x = (s == 0 ? x0 : s == 1 ? x1 : s == 2 ? x2 : x3);
    const float* p = (s == 0 ? p0 : s == 1 ? p1 : s == 2 ? p2 : p3);

    const int c0 = chunk * CCHUNK;
    const float* xb = x + ((size_t)b * C + c0) * hw + i;
    const float* pb = p + ((size_t)b * C + c0) * hw + i;
    const float* wq = g_wq + (s * BT + b) * C + c0;
    const float* yv = g_y  + (s * BT + b) * C + c0;
    float* vout = out + c_voutoff[s] + ((size_t)b * C + c0) * hw + i;

    float4 acc = make_float4(0.f, 0.f, 0.f, 0.f);
    #pragma unroll 4
    for (int c = 0; c < CCHUNK; c += 4) {
        const float* xc = xb + (size_t)c * hw;
        const float* pc = pb + (size_t)c * hw;
        float4 xv0 = ld4(xc);
        float4 pv0 = ld4cs(pc);
        float4 xv1 = ld4(xc + hw);
        float4 pv1 = ld4cs(pc + hw);
        float4 xv2 = ld4(xc + 2 * (size_t)hw);
        float4 pv2 = ld4cs(pc + 2 * (size_t)hw);
        float4 xv3 = ld4(xc + 3 * (size_t)hw);
        float4 pv3 = ld4cs(pc + 3 * (size_t)hw);
        float4 w4 = ld4(wq + c);
        float4 y4 = ld4(yv + c);

        acc.x = fmaf(xv0.x + pv0.x, w4.x, acc.x);
        acc.y = fmaf(xv0.y + pv0.y, w4.x, acc.y);
        acc.z = fmaf(xv0.z + pv0.z, w4.x, acc.z);
        acc.w = fmaf(xv0.w + pv0.w, w4.x, acc.w);
        acc.x = fmaf(xv1.x + pv1.x, w4.y, acc.x);
        acc.y = fmaf(xv1.y + pv1.y, w4.y, acc.y);
        acc.z = fmaf(xv1.z + pv1.z, w4.y, acc.z);
        acc.w = fmaf(xv1.w + pv1.w, w4.y, acc.w);
        acc.x = fmaf(xv2.x + pv2.x, w4.z, acc.x);
        acc.y = fmaf(xv2.y + pv2.y, w4.z, acc.y);
        acc.z = fmaf(xv2.z + pv2.z, w4.z, acc.z);
        acc.w = fmaf(xv2.w + pv2.w, w4.z, acc.w);
        acc.x = fmaf(xv3.x + pv3.x, w4.w, acc.x);
        acc.y = fmaf(xv3.y + pv3.y, w4.w, acc.y);
        acc.z = fmaf(xv3.z + pv3.z, w4.w, acc.z);
        acc.w = fmaf(xv3.w + pv3.w, w4.w, acc.w);

        float* vc = vout + (size_t)c * hw;
        __stcs((float4*)vc,                     make_float4(y4.x, y4.x, y4.x, y4.x));
        __stcs((float4*)(vc + hw),              make_float4(y4.y, y4.y, y4.y, y4.y));
        __stcs((float4*)(vc + 2 * (size_t)hw),  make_float4(y4.z, y4.z, y4.z, y4.z));
        __stcs((float4*)(vc + 3 * (size_t)hw),  make_float4(y4.w, y4.w, y4.w, y4.w));
    }
    int gp = c_pixoff[s] + b * hw + i;
    *(float4*)(g_simp + chunk * NPIX_TOTAL + gp) = acc;
}

// ---------------------------------------------------------------------------
// K2b: parallel exp (NO max-sub; sim ~N(0,3.5^2), far from fp32 exp overflow).
// float4 path: thread reduces 4 pixels x 12 chunk arrays. 110 blocks.
// ---------------------------------------------------------------------------
__global__ __launch_bounds__(256)
void k_simexp()
{
    int blk = blockIdx.x;
    int s;
    if      (blk < 70)  s = 0;
    else if (blk < 90)  s = 1;
    else if (blk < 100) s = 2;
    else                s = 3;

    const int nb    = c_senb[s];
    const int local = blk - c_seoff[s];
    const int b     = local / nb;
    const int bi    = local - b * nb;
    const int hw    = c_hw[s];
    const int off   = c_pixoff[s] + b * hw;

    const int tid  = threadIdx.x;
    const int lane = tid & 31;
    const int warp = tid >> 5;
    const int i    = bi * 1024 + tid * 4;      // hw always multiple of 4

    __shared__ float sh_red[8];

    float esum = 0.f;
    if (i < hw) {
        int g = off + i;
        float4 v = ld4(g_simp + g);
        #pragma unroll
        for (int k = 1; k < NCHUNK; k++) {
            float4 t = ld4(g_simp + k * NPIX_TOTAL + g);
            v.x += t.x; v.y += t.y; v.z += t.z; v.w += t.w;
        }
        float4 e = make_float4(__expf(v.x), __expf(v.y), __expf(v.z), __expf(v.w));
        *(float4*)(g_p + g) = e;
        esum = (e.x + e.y) + (e.z + e.w);
    }
    float ssum = warp_sum(esum);
    if (lane == 0) sh_red[warp] = ssum;
    __syncthreads();
    if (tid < 8) {
        float v = sh_red[tid];
        #pragma unroll
        for (int o = 4; o > 0; o >>= 1) v += __shfl_down_sync(0xffu, v, o);
        if (tid == 0) g_psum[blk] = v;
    }
}

// ---------------------------------------------------------------------------
// K3: xbar partials (UNNORMALIZED). Block = (stage, b, 16-ch group, i-seg of
// 1600). Warp handles 2 channels. 46-reg measured-best variant.
// ---------------------------------------------------------------------------
#define CG        16
#define NGROUPS   (C / CG)          // 24

__global__ __launch_bounds__(256)
void k_xbar(const float* __restrict__ x0, const float* __restrict__ x1,
            const float* __restrict__ x2, const float* __restrict__ x3)
{
    int blk = blockIdx.x;
    int s;
    if      (blk < 960)  s = 0;
    else if (blk < 1200) s = 1;
    else if (blk < 1440) s = 2;
    else                 s = 3;

    const int local = blk - c_xboff[s];
    const int nseg  = c_nseg[s];
    const int seg   = local % nseg;
    const int rest  = local / nseg;
    const int cg    = rest % NGROUPS;
    const int b     = rest / NGROUPS;
    const int hw    = c_hw[s];
    const int i0    = seg * ISEG;
    const int ilen  = (hw - i0 < ISEG) ? (hw - i0) : ISEG;

    const int lane = threadIdx.x & 31;
    const int warp = threadIdx.x >> 5;

    const float* x  = (s == 0 ? x0 : s == 1 ? x1 : s == 2 ? x2 : x3);
    const float* p  = g_p + c_pixoff[s] + b * hw + i0;

    const int c0 = cg * CG + warp * 2;
    const float* xc0 = x + ((size_t)b * C + c0) * hw + i0;
    const float* xc1 = xc0 + hw;

    float a00 = 0.f, a01 = 0.f, a02 = 0.f, a03 = 0.f;
    float a10 = 0.f, a11 = 0.f, a12 = 0.f, a13 = 0.f;
    for (int i = lane * 4; i < ilen; i += 128) {
        float4 pv  = ld4(p + i);
        float4 v0  = ld4(xc0 + i);
        float4 v1  = ld4(xc1 + i);
        a00 = fmaf(pv.x, v0.x, a00);
        a01 = fmaf(pv.y, v0.y, a01);
        a02 = fmaf(pv.z, v0.z, a02);
        a03 = fmaf(pv.w, v0.w, a03);
        a10 = fmaf(pv.x, v1.x, a10);
        a11 = fmaf(pv.y, v1.y, a11);
        a12 = fmaf(pv.z, v1.z, a12);
        a13 = fmaf(pv.w, v1.w, a13);
    }
    float r0 = warp_sum((a00 + a01) + (a02 + a03));
    float r1 = warp_sum((a10 + a11) + (a12 + a13));
    if (lane == 0) {
        int base = seg * (NSTG * BT * C) + (s * BT + b) * C + c0;
        g_xbarp[base]     = r0;
        g_xbarp[base + 1] = r1;
    }
}

// ---------------------------------------------------------------------------
// K4: reconstruct rinv from per-block exp sums (fixed order), combine xbar
// partials (fixed order), then aout = bco + Wco@(Wv@xbar).
// ---------------------------------------------------------------------------
__global__ __launch_bounds__(C)
void k_aout(const float* __restrict__ v_w,
            const float* __restrict__ ctx_out_w,
            const float* __restrict__ ctx_out_b,
            float* __restrict__ out)
{
    int s = blockIdx.x / BT;
    int b = blockIdx.x % BT;
    __shared__ float sh_ps[32];
    __shared__ float sh_xb[C];
    __shared__ float sh_part[DH * 6];
    __shared__ float sh_t[DH];

    const int tid = threadIdx.x;
    const int sb  = s * BT + b;
    const int nb  = c_senb[s];

    if (tid < nb) sh_ps[tid] = g_psum[c_seoff[s] + b * nb + tid];
    __syncthreads();

    // every thread computes the identical fixed-order sum -> identical rinv
    float ssum = 0.f;
    for (int k = 0; k < nb; k++) ssum += sh_ps[k];
    const float rinv = 1.f / ssum;

    // combine segment partials (fixed order), normalize
    {
        int idx = sb * C + tid;
        float v = g_xbarp[idx];
        if (s == 0) {
            v = (v + g_xbarp[NSTG * BT * C + idx]) +
                (g_xbarp[2 * NSTG * BT * C + idx] + g_xbarp[3 * NSTG * BT * C + idx]);
        }
        sh_xb[tid] = v * rinv;
    }
    __syncthreads();

    // t[d] = Wv[d,:] @ xbar
    {
        int chunk = tid >> 6;
        int d     = tid & 63;
        const float* wv  = v_w + ((size_t)s * DH + d) * C + chunk * 64;
        const float* vec = sh_xb + chunk * 64;
        float acc = 0.f;
        #pragma unroll
        for (int k = 0; k < 64; k += 4) {
            float4 w = ld4(wv + k);
            float4 u = ld4(vec + k);
            acc += w.x * u.x + w.y * u.y + w.z * u.z + w.w * u.w;
        }
        sh_part[d * 6 + chunk] = acc;
    }
    __syncthreads();
    if (tid < DH) {
        const float* pp = sh_part + tid * 6;
        sh_t[tid] = ((pp[0] + pp[1]) + (pp[2] + pp[3])) + (pp[4] + pp[5]);
    }
    __syncthreads();

    // aout[c] = Wco[c,:] @ t + bco
    {
        const float* wco = ctx_out_w + ((size_t)s * C + tid) * DH;
        float acc = 0.f;
        #pragma unroll
        for (int d = 0; d < DH; d += 4) {
            float4 w = ld4(wco + d);
            float4 t = ld4(sh_t + d);
            acc += w.x * t.x + w.y * t.y + w.z * t.z + w.w * t.w;
        }
        out[VOUT_TOTAL + sb * C + tid] = acc + ctx_out_b[s * C + tid];
    }
}

// ---------------------------------------------------------------------------
extern "C" void kernel_launch(void* const* d_in, const int* in_sizes, int n_in,
                              void* d_out, int out_size)
{
    const float *fm[NSTG], *ps[NSTG], *au[NSTG];
    bool dict_order = (in_sizes[1] == in_sizes[0]);
    if (dict_order) {
        for (int s = 0; s < NSTG; s++) {
            fm[s] = (const float*)d_in[3 * s + 0];
            ps[s] = (const float*)d_in[3 * s + 1];
            au[s] = (const float*)d_in[3 * s + 2];
        }
    } else {
        for (int s = 0; s < NSTG; s++) {
            fm[s] = (const float*)d_in[s];
            au[s] = (const float*)d_in[4 + s];
            ps[s] = (const float*)d_in[8 + s];
        }
    }
    const float* ctx_proj_w = (const float*)d_in[12];
    const float* ctx_proj_b = (const float*)d_in[13];
    const float* pos_emb    = (const float*)d_in[14];
    const float* qk_w       = (const float*)d_in[15];
    const float* ctx_qk_w   = (const float*)d_in[16];
    const float* v_w        = (const float*)d_in[17];
    const float* ctx_v_w    = (const float*)d_in[18];
    const float* out_w      = (const float*)d_in[19];
    const float* out_b      = (const float*)d_in[20];
    const float* ctx_out_w  = (const float*)d_in[21];
    const float* ctx_out_b  = (const float*)d_in[22];

    float* out = (float*)d_out;

    k_setup<<<NSTG * BT, C>>>(au[0], au[1], au[2], au[3],
                              ctx_proj_w, ctx_proj_b, pos_emb,
                              qk_w, ctx_qk_w, ctx_v_w, out_w, out_b);

    k_sim_vout<<<(NUNITS + 255) / 256, 256>>>(fm[0], fm[1], fm[2], fm[3],
                                              ps[0], ps[1], ps[2], ps[3], out);

    k_simexp<<<SE_BLOCKS, 256>>>();

    k_xbar<<<XBAR_BLOCKS, 256>>>(fm[0], fm[1], fm[2], fm[3]);

    k_aout<<<NSTG * BT, C>>>(v_w, ctx_out_w, ctx_out_b, out);
}